// round 13
// baseline (speedup 1.0000x reference)
#include <cuda_runtime.h>
#include <cstdint>

// Problem constants
#define T_STEPS 2048
#define BATCH   16
#define DIM     1024

constexpr size_t SZ_TBD  = (size_t)T_STEPS * BATCH * DIM;        // 33,554,432
constexpr size_t SZ_T1BD = (size_t)(T_STEPS + 1) * BATCH * DIM;  // 33,570,816

constexpr size_t OUT_OFF   = 0;
constexpr size_t LOGH_OFF  = SZ_TBD;
constexpr size_t SIGNH_OFF = SZ_TBD + SZ_T1BD;
constexpr size_t HLIN_OFF  = SZ_TBD + 2 * SZ_T1BD;               // total 134,250,496

#define RCTAS 128
#define CPC   8    // output columns per CTA

// Scratch: h broadcast ping-pong + per-CTA flags (A/G never leave SMEM)
__device__ float g_hf[2][BATCH * DIM];
__device__ unsigned g_flags[RCTAS * 8];

// ---- primitives -----------------------------------------------------------
__device__ __forceinline__ void st_release_gpu(unsigned* p, unsigned v) {
    asm volatile("st.release.gpu.global.u32 [%0], %1;" :: "l"(p), "r"(v) : "memory");
}
__device__ __forceinline__ unsigned ld_acquire_gpu(const unsigned* p) {
    unsigned v;
    asm volatile("ld.acquire.gpu.global.u32 %0, [%1];" : "=r"(v) : "l"(p) : "memory");
    return v;
}
__device__ __forceinline__ void cp_async16(uint32_t dst, const void* src) {
    asm volatile("cp.async.cg.shared.global [%0], [%1], 16;" :: "r"(dst), "l"(src));
}
__device__ __forceinline__ void cp_async_commit() {
    asm volatile("cp.async.commit_group;");
}
template <int N>
__device__ __forceinline__ void cp_async_wait() {
    asm volatile("cp.async.wait_group %0;" :: "n"(N));
}
#define BAR_REC()  asm volatile("bar.sync 1, 256;" ::: "memory")

// ---------------------------------------------------------------------------
// Init: flags, h0, log_h[0]/sign_h[0] rows
// ---------------------------------------------------------------------------
__global__ void init_kernel(float* __restrict__ d_out) {
    int tid = blockIdx.x * blockDim.x + threadIdx.x;
    if (tid < RCTAS * 8) g_flags[tid] = 0u;
    const int n = BATCH * DIM;
    for (int i = tid; i < n; i += gridDim.x * blockDim.x) {
        g_hf[0][i] = 0.0f;
        d_out[LOGH_OFF  + i] = -1e4f;   // LOG_ZERO
        d_out[SIGNH_OFF + i] = 1.0f;
    }
}

// ---------------------------------------------------------------------------
// Fused persistent kernel: 128 CTAs x 512 threads (16 warps).
//   warps 0-7 : recurrence (arithmetic BIT-IDENTICAL to the passing R4 kernel)
//   warps 8-15: GEMM producer — 256 threads, each owns ONE output of
//               A[t+2]/G[t+2] for this CTA's 8 cols, computed as a strict
//               ascending-k serial fp32 FMA chain from 0 + one bias add:
//               BIT-IDENTICAL to R4's gemm_nt_kernel per-output arithmetic.
// A/G never written to global memory (3-slot SMEM ring).
//
// SMEM (floats):
//   hs  [16*1024]      @ 0      (64 KB)   h broadcast
//   Rs  [ 8*1024]      @ 16384  (32 KB)   R_h slice
//   Ws  [16*1028]      @ 24576  (64.25KB) W slice: rows 0-7 = W_x, 8-15 = W_d
//   AGr [3][16][16]    @ 41024  ( 3 KB)   A/G ring (slot, batch, col16)
// ---------------------------------------------------------------------------
#define HS_OFF   0
#define RS_OFF   16384
#define WS_OFF   24576
#define WPITCH   1028
#define AGR_OFF  (WS_OFF + 16 * WPITCH)   // 41024
#define SM_FLOATS (AGR_OFF + 768)          // 41792
#define SM_BYTES  (SM_FLOATS * 4)          // 167168

__global__ __launch_bounds__(512, 1)
void fused_kernel(const float* __restrict__ x,
                  const float* __restrict__ W_x, const float* __restrict__ W_d,
                  const float* __restrict__ Rh,
                  const float* __restrict__ b,   const float* __restrict__ b_d,
                  const float* __restrict__ b_gate, float* __restrict__ d_out)
{
    extern __shared__ float sm[];
    float* hs  = sm + HS_OFF;
    float* Rs  = sm + RS_OFF;
    float* Ws  = sm + WS_OFF;
    float* AGr = sm + AGR_OFF;

    const int cta  = blockIdx.x;
    const int tid  = threadIdx.x;
    const int warp = tid >> 5;
    const int lane = tid & 31;
    const bool isRec = (warp < 8);

    // ---- R slice into SMEM (all 512 threads) ----
    {
        const float4* src = (const float4*)(Rh + (size_t)cta * CPC * DIM);
        float4* dst = (float4*)Rs;
        for (int i = tid; i < CPC * DIM / 4; i += 512) dst[i] = src[i];
    }
    // ---- W slice into SMEM: Ws[c][k], c 0-7 = W_x rows, 8-15 = W_d rows ----
    {
        for (int i = tid; i < 16 * 256; i += 512) {   // float4 units
            const int c  = i >> 8;          // 0..15
            const int k4 = i & 255;         // 0..255
            const float* src = (c < 8)
                ? (W_x + (size_t)(cta * CPC + c) * DIM + k4 * 4)
                : (W_d + (size_t)(cta * CPC + (c - 8)) * DIM + k4 * 4);
            *(float4*)&Ws[c * WPITCH + k4 * 4] = __ldg((const float4*)src);
        }
    }

    // ================= recurrent-role setup (warps 0-7) =================
    const int bb = warp & 3;
    const int dd = warp >> 2;                 // 0..1 (valid only warp<8)
    const int ep_b  = bb * 4 + (lane >> 2);
    const int ep_lc = (dd & 1) * 4 + (lane & 3);   // local col 0..7
    const int ep_d  = cta * CPC + ep_lc;
    float bg = 0.f, hprev = 0.f, pf_x = 0.f;
    int cp_row[4], cp_c4[4];
    if (isRec) {
        if (lane < 16) {
            bg  = b_gate[ep_d];
            pf_x = __ldg(&x[(size_t)ep_b * DIM + ep_d]);   // x for t=0
        }
#pragma unroll
        for (int j = 0; j < 4; j++) {
            int f = tid + j * 256;
            cp_row[j] = f >> 6;
            cp_c4[j]  = f & 63;
        }
    }
    const uint32_t hs_u32 = (uint32_t)__cvta_generic_to_shared(hs);

    // ================= GEMM-role setup (warps 8-15) =====================
    const int tg   = tid - 256;               // 0..255 (valid only !isRec)
    const int grow = tg >> 4;                 // batch row 0..15
    const int gcol = tg & 15;                 // col16: 0-7 A, 8-15 G
    float gbias = 0.f;
    if (!isRec) {
        gbias = (gcol < 8) ? __ldg(&b[cta * CPC + gcol])
                           : __ldg(&b_d[cta * CPC + (gcol - 8)]);
    }

    __syncthreads();

    for (int t = -2; t < T_STEPS; t++) {
        const int t2 = t + 2;

        if (isRec) {
            if (t >= 0) {
                const int cur = t & 1, nxt = cur ^ 1;

                // ---- 0) off-chain: A/G from SMEM ring + precompute ----
                float a_t = 0.f, delta = 0.f, omdh = 0.f, zbase = 0.f;
                if (lane < 16) {
                    const int slot = (t % 3) * 256 + ep_b * 16;
                    a_t = AGr[slot + ep_lc];
                    const float g_t = AGr[slot + 8 + ep_lc];
                    delta = 1.0f / (1.0f + expf(-g_t));
                    omdh  = (1.0f - delta) * hprev;
                    zbase = pf_x + bg;
                }

                // ---- 1) issue h broadcast: 4 cp.async chunk-groups ----
                {
                    const float4* src = (const float4*)g_hf[cur];
#pragma unroll
                    for (int u = 0; u < 4; u++) {
#pragma unroll
                        for (int j = 0; j < 4; j++) {
                            const int off = cp_row[j] * 256 + u * 64 + cp_c4[j];
                            cp_async16(hs_u32 + (uint32_t)off * 16, src + off);
                        }
                        cp_async_commit();
                    }
                }

                // ---- 2) dot (h from hs, R from Rs), chunk-overlapped ----
                float acc[4][4];
#pragma unroll
                for (int i = 0; i < 4; i++)
#pragma unroll
                    for (int j = 0; j < 4; j++) acc[i][j] = 0.0f;

#pragma unroll
                for (int u = 0; u < 4; u++) {
                    if      (u == 0) cp_async_wait<3>();
                    else if (u == 1) cp_async_wait<2>();
                    else if (u == 2) cp_async_wait<1>();
                    else             cp_async_wait<0>();
                    BAR_REC();
#pragma unroll
                    for (int v = 0; v < 2; v++) {
                        const int ur = u * 2 + v;
                        const int k  = ur * 128 + lane * 4;
                        float4 hv[4], rv[4];
#pragma unroll
                        for (int i = 0; i < 4; i++)
                            hv[i] = *(const float4*)&hs[(bb * 4 + i) * DIM + k];
#pragma unroll
                        for (int j = 0; j < 4; j++)
                            rv[j] = *(const float4*)&Rs[(dd * 4 + j) * DIM + k];
#pragma unroll
                        for (int i = 0; i < 4; i++)
#pragma unroll
                            for (int j = 0; j < 4; j++) {
                                acc[i][j] += hv[i].x * rv[j].x;
                                acc[i][j] += hv[i].y * rv[j].y;
                                acc[i][j] += hv[i].z * rv[j].z;
                                acc[i][j] += hv[i].w * rv[j].w;
                            }
                    }
                }

                // ---- 3) folded shuffle reduce: value i*4+j -> lane ----
                float* v16 = &acc[0][0];
#pragma unroll
                for (int v = 0; v < 16; v++) v16[v] += __shfl_xor_sync(0xffffffffu, v16[v], 16);
#pragma unroll
                for (int v = 0; v < 16; v++) v16[v] += __shfl_xor_sync(0xffffffffu, v16[v], 8);
                float v8[8];
#pragma unroll
                for (int j = 0; j < 8; j++) v8[j] = (lane & 8) ? v16[8 + j] : v16[j];
#pragma unroll
                for (int j = 0; j < 8; j++) v8[j] += __shfl_xor_sync(0xffffffffu, v8[j], 4);
                float v4[4];
#pragma unroll
                for (int j = 0; j < 4; j++) v4[j] = (lane & 4) ? v8[4 + j] : v8[j];
#pragma unroll
                for (int j = 0; j < 4; j++) v4[j] += __shfl_xor_sync(0xffffffffu, v4[j], 2);
                float v2[2];
#pragma unroll
                for (int j = 0; j < 2; j++) v2[j] = (lane & 2) ? v4[2 + j] : v4[j];
#pragma unroll
                for (int j = 0; j < 2; j++) v2[j] += __shfl_xor_sync(0xffffffffu, v2[j], 1);
                const float dot = (lane & 1) ? v2[1] : v2[0];

                // ---- 4) critical chain: tanh -> h_new -> publish ----
                float hn = 0.0f;
                if (lane < 16) {
                    const float v = a_t + dot;
                    const float cand = tanhf(v);
                    hn = fmaf(delta, cand, omdh);
                    __stcg(&g_hf[nxt][ep_b * DIM + ep_d], hn);
                    __threadfence();
                }
                BAR_REC();
                if (tid == 0) st_release_gpu(&g_flags[cta * 8], (unsigned)(t + 1));

                // ---- 5) off-chain work inside the barrier-wait window ----
                if (lane < 16) {
                    const size_t idx = ((size_t)t * BATCH + ep_b) * DIM + ep_d;
                    const float lg = logf(fabsf(hn) + 1e-12f);
                    const float sg = (hn >= 0.0f) ? 1.0f : -1.0f;
                    const float z  = hn + zbase;
                    const float sig = 1.0f / (1.0f + expf(-z));
                    d_out[OUT_OFF + idx]                         = hn * (z * sig);
                    d_out[LOGH_OFF + idx + (size_t)BATCH * DIM]  = lg;
                    d_out[SIGNH_OFF + idx + (size_t)BATCH * DIM] = sg;
                    d_out[HLIN_OFF + idx]                        = hn;
                    hprev = hn;

                    const int tn2 = (t + 1 < T_STEPS) ? t + 1 : t;
                    pf_x = __ldg(&x[((size_t)tn2 * BATCH + ep_b) * DIM + ep_d]);
                }

                // ---- 6) one-hop barrier: poll all 128 producer flags ----
                if (tid < RCTAS) {
                    while (ld_acquire_gpu(&g_flags[tid * 8]) < (unsigned)(t + 1)) { }
                }
            }
        } else {
            // ===== GEMM producer: one output, serial ascending-k chain =====
            // BIT-IDENTICAL to R4's gemm_nt_kernel arithmetic:
            //   s = 0; for k=0..1023: s = fma(x[row][k], W[col][k], s); s += bias
            if (t2 < T_STEPS) {
                const float* xrow = x + ((size_t)t2 * BATCH + grow) * DIM;
                const float* wrow = Ws + gcol * WPITCH;
                float s = 0.0f;
#pragma unroll 8
                for (int k4 = 0; k4 < 256; k4++) {
                    const float4 xv = __ldg((const float4*)xrow + k4);
                    const float4 wv = *(const float4*)(wrow + k4 * 4);
                    s = fmaf(xv.x, wv.x, s);
                    s = fmaf(xv.y, wv.y, s);
                    s = fmaf(xv.z, wv.z, s);
                    s = fmaf(xv.w, wv.w, s);
                }
                s += gbias;
                AGr[(t2 % 3) * 256 + grow * 16 + gcol] = s;
            }
        }

        __syncthreads();   // step boundary: orders AGr ring handoff
    }
}

// ---------------------------------------------------------------------------
extern "C" void kernel_launch(void* const* d_in, const int* in_sizes, int n_in,
                              void* d_out, int out_size)
{
    const float* x       = (const float*)d_in[0];
    const float* W_x     = (const float*)d_in[1];
    const float* R_h     = (const float*)d_in[2];
    const float* W_delta = (const float*)d_in[3];
    const float* b       = (const float*)d_in[4];
    const float* b_delta = (const float*)d_in[5];
    const float* b_gate  = (const float*)d_in[6];
    float* out = (float*)d_out;

    cudaFuncSetAttribute(fused_kernel,
                         cudaFuncAttributeMaxDynamicSharedMemorySize, SM_BYTES);

    init_kernel<<<64, 256>>>(out);
    fused_kernel<<<RCTAS, 512, SM_BYTES>>>(x, W_x, W_delta, R_h, b, b_delta,
                                           b_gate, out);
}

// round 14
// speedup vs baseline: 2.5028x; 2.5028x over previous
#include <cuda_runtime.h>
#include <cstdint>

// Problem constants
#define T_STEPS 2048
#define BATCH   16
#define DIM     1024

constexpr size_t SZ_TBD  = (size_t)T_STEPS * BATCH * DIM;        // 33,554,432
constexpr size_t SZ_T1BD = (size_t)(T_STEPS + 1) * BATCH * DIM;  // 33,570,816

constexpr size_t OUT_OFF   = 0;
constexpr size_t LOGH_OFF  = SZ_TBD;
constexpr size_t SIGNH_OFF = SZ_TBD + SZ_T1BD;
constexpr size_t HLIN_OFF  = SZ_TBD + 2 * SZ_T1BD;               // total 134,250,496

#define RCTAS 128
#define CPC   8    // output columns per CTA
#define NTHR  384  // 8 rec warps + 4 gemm warps

// Scratch: h broadcast ping-pong + per-CTA flags (A/G never leave SMEM)
__device__ float g_hf[2][BATCH * DIM];
__device__ unsigned g_flags[RCTAS * 8];

// ---- primitives -----------------------------------------------------------
__device__ __forceinline__ void st_release_gpu(unsigned* p, unsigned v) {
    asm volatile("st.release.gpu.global.u32 [%0], %1;" :: "l"(p), "r"(v) : "memory");
}
__device__ __forceinline__ unsigned ld_acquire_gpu(const unsigned* p) {
    unsigned v;
    asm volatile("ld.acquire.gpu.global.u32 %0, [%1];" : "=r"(v) : "l"(p) : "memory");
    return v;
}
__device__ __forceinline__ void cp_async16(uint32_t dst, const void* src) {
    asm volatile("cp.async.cg.shared.global [%0], [%1], 16;" :: "r"(dst), "l"(src));
}
__device__ __forceinline__ void cp_async_commit() {
    asm volatile("cp.async.commit_group;");
}
template <int N>
__device__ __forceinline__ void cp_async_wait() {
    asm volatile("cp.async.wait_group %0;" :: "n"(N));
}
#define BAR_REC()  asm volatile("bar.sync 1, 256;" ::: "memory")
#define BAR_GEMM() asm volatile("bar.sync 2, 128;" ::: "memory")

// ---------------------------------------------------------------------------
// Init: flags, h0, log_h[0]/sign_h[0] rows
// ---------------------------------------------------------------------------
__global__ void init_kernel(float* __restrict__ d_out) {
    int tid = blockIdx.x * blockDim.x + threadIdx.x;
    if (tid < RCTAS * 8) g_flags[tid] = 0u;
    const int n = BATCH * DIM;
    for (int i = tid; i < n; i += gridDim.x * blockDim.x) {
        g_hf[0][i] = 0.0f;
        d_out[LOGH_OFF  + i] = -1e4f;   // LOG_ZERO
        d_out[SIGNH_OFF + i] = 1.0f;
    }
}

// ---------------------------------------------------------------------------
// Fused persistent kernel: 128 CTAs x 384 threads (12 warps).
//   warps 0-7 : recurrence — arithmetic BIT-IDENTICAL to the passing R4 kernel
//   warps 8-11: GEMM producer — 128 threads; thread (row, c) owns BOTH
//               A[t+2][row][c] and G[t+2][row][c] as two independent strict
//               ascending-k serial fp32 FMA chains (ILP=2), bit-identical to
//               R4's gemm per-output arithmetic.  x[t+2] staged through a
//               2-slot SMEM chunk ring via cp.async (256 k per chunk); W
//               resident in SMEM.  A/G handed over via a 3-slot SMEM ring.
//
// SMEM (floats):
//   hs  [16*1024]        @ 0      (64 KB)     h broadcast
//   Rs  [ 8*1024]        @ 16384  (32 KB)     R_h slice
//   Ws  [16*1028]        @ 24576  (64.25 KB)  rows 0-7 W_x, 8-15 W_delta
//   xs  [2][16*260]      @ 41024  (32.5 KB)   x chunk ring (pitch 260)
//   AGr [3][16][16]      @ 49344  ( 3 KB)     A/G ring (slot, batch, col16)
// ---------------------------------------------------------------------------
#define HS_OFF   0
#define RS_OFF   16384
#define WS_OFF   24576
#define WPITCH   1028
#define XS_OFF   41024
#define XPITCH   260
#define XSLOTF   (16 * XPITCH)     // 4160 floats per slot
#define AGR_OFF  49344
#define SM_FLOATS 50112
#define SM_BYTES  (SM_FLOATS * 4)  // 200448

__global__ __launch_bounds__(NTHR, 1)
void fused_kernel(const float* __restrict__ x,
                  const float* __restrict__ W_x, const float* __restrict__ W_d,
                  const float* __restrict__ Rh,
                  const float* __restrict__ b,   const float* __restrict__ b_d,
                  const float* __restrict__ b_gate, float* __restrict__ d_out)
{
    extern __shared__ float sm[];
    float* hs  = sm + HS_OFF;
    float* Rs  = sm + RS_OFF;
    float* Ws  = sm + WS_OFF;
    float* xs  = sm + XS_OFF;
    float* AGr = sm + AGR_OFF;

    const int cta  = blockIdx.x;
    const int tid  = threadIdx.x;
    const int warp = tid >> 5;
    const int lane = tid & 31;
    const bool isRec = (warp < 8);

    // ---- R slice into SMEM (all threads) ----
    {
        const float4* src = (const float4*)(Rh + (size_t)cta * CPC * DIM);
        float4* dst = (float4*)Rs;
        for (int i = tid; i < CPC * DIM / 4; i += NTHR) dst[i] = src[i];
    }
    // ---- W slice into SMEM: Ws[c][k], c 0-7 = W_x rows, 8-15 = W_d rows ----
    {
        for (int i = tid; i < 16 * 256; i += NTHR) {   // float4 units
            const int c  = i >> 8;          // 0..15
            const int k4 = i & 255;         // 0..255
            const float* src = (c < 8)
                ? (W_x + (size_t)(cta * CPC + c) * DIM + k4 * 4)
                : (W_d + (size_t)(cta * CPC + (c - 8)) * DIM + k4 * 4);
            *(float4*)&Ws[c * WPITCH + k4 * 4] = __ldg((const float4*)src);
        }
    }

    const uint32_t hs_u32 = (uint32_t)__cvta_generic_to_shared(hs);
    const uint32_t xs_u32 = (uint32_t)__cvta_generic_to_shared(xs);

    // ================= recurrent-role setup (warps 0-7) =================
    const int bb = warp & 3;
    const int dd = warp >> 2;                 // 0..1 (valid only warp<8)
    const int ep_b  = bb * 4 + (lane >> 2);
    const int ep_lc = (dd & 1) * 4 + (lane & 3);   // local col 0..7
    const int ep_d  = cta * CPC + ep_lc;
    float bg = 0.f, hprev = 0.f, pf_x = 0.f;
    int cp_row[4], cp_c4[4];
    if (isRec) {
        if (lane < 16) {
            bg  = b_gate[ep_d];
            pf_x = __ldg(&x[(size_t)ep_b * DIM + ep_d]);   // x for t=0
        }
#pragma unroll
        for (int j = 0; j < 4; j++) {
            int f = tid + j * 256;
            cp_row[j] = f >> 6;
            cp_c4[j]  = f & 63;
        }
    }

    // ================= GEMM-role setup (warps 8-11) =====================
    const int tg   = tid - 256;               // 0..127 (valid only !isRec)
    const int grow = tg & 15;                 // batch row 0..15
    const int gc   = ((tg >> 5) << 1) + ((tg & 31) >> 4);  // col 0..7
    float gba = 0.f, gbd = 0.f;
    if (!isRec) {
        gba = __ldg(&b[cta * CPC + gc]);
        gbd = __ldg(&b_d[cta * CPC + gc]);
    }

    __syncthreads();

    for (int t = -2; t < T_STEPS; t++) {
        const int t2 = t + 2;

        if (isRec) {
            if (t >= 0) {
                const int cur = t & 1, nxt = cur ^ 1;

                // ---- 0) off-chain: A/G from SMEM ring + precompute ----
                float a_t = 0.f, delta = 0.f, omdh = 0.f, zbase = 0.f;
                if (lane < 16) {
                    const int slot = (t % 3) * 256 + ep_b * 16;
                    a_t = AGr[slot + ep_lc];
                    const float g_t = AGr[slot + 8 + ep_lc];
                    delta = 1.0f / (1.0f + expf(-g_t));
                    omdh  = (1.0f - delta) * hprev;
                    zbase = pf_x + bg;
                }

                // ---- 1) issue h broadcast: 4 cp.async chunk-groups ----
                {
                    const float4* src = (const float4*)g_hf[cur];
#pragma unroll
                    for (int u = 0; u < 4; u++) {
#pragma unroll
                        for (int j = 0; j < 4; j++) {
                            const int off = cp_row[j] * 256 + u * 64 + cp_c4[j];
                            cp_async16(hs_u32 + (uint32_t)off * 16, src + off);
                        }
                        cp_async_commit();
                    }
                }

                // ---- 2) dot (h from hs, R from Rs), chunk-overlapped ----
                float acc[4][4];
#pragma unroll
                for (int i = 0; i < 4; i++)
#pragma unroll
                    for (int j = 0; j < 4; j++) acc[i][j] = 0.0f;

#pragma unroll
                for (int u = 0; u < 4; u++) {
                    if      (u == 0) cp_async_wait<3>();
                    else if (u == 1) cp_async_wait<2>();
                    else if (u == 2) cp_async_wait<1>();
                    else             cp_async_wait<0>();
                    BAR_REC();
#pragma unroll
                    for (int v = 0; v < 2; v++) {
                        const int ur = u * 2 + v;
                        const int k  = ur * 128 + lane * 4;
                        float4 hv[4], rv[4];
#pragma unroll
                        for (int i = 0; i < 4; i++)
                            hv[i] = *(const float4*)&hs[(bb * 4 + i) * DIM + k];
#pragma unroll
                        for (int j = 0; j < 4; j++)
                            rv[j] = *(const float4*)&Rs[(dd * 4 + j) * DIM + k];
#pragma unroll
                        for (int i = 0; i < 4; i++)
#pragma unroll
                            for (int j = 0; j < 4; j++) {
                                acc[i][j] += hv[i].x * rv[j].x;
                                acc[i][j] += hv[i].y * rv[j].y;
                                acc[i][j] += hv[i].z * rv[j].z;
                                acc[i][j] += hv[i].w * rv[j].w;
                            }
                    }
                }

                // ---- 3) folded shuffle reduce: value i*4+j -> lane ----
                float* v16 = &acc[0][0];
#pragma unroll
                for (int v = 0; v < 16; v++) v16[v] += __shfl_xor_sync(0xffffffffu, v16[v], 16);
#pragma unroll
                for (int v = 0; v < 16; v++) v16[v] += __shfl_xor_sync(0xffffffffu, v16[v], 8);
                float v8[8];
#pragma unroll
                for (int j = 0; j < 8; j++) v8[j] = (lane & 8) ? v16[8 + j] : v16[j];
#pragma unroll
                for (int j = 0; j < 8; j++) v8[j] += __shfl_xor_sync(0xffffffffu, v8[j], 4);
                float v4[4];
#pragma unroll
                for (int j = 0; j < 4; j++) v4[j] = (lane & 4) ? v8[4 + j] : v8[j];
#pragma unroll
                for (int j = 0; j < 4; j++) v4[j] += __shfl_xor_sync(0xffffffffu, v4[j], 2);
                float v2[2];
#pragma unroll
                for (int j = 0; j < 2; j++) v2[j] = (lane & 2) ? v4[2 + j] : v4[j];
#pragma unroll
                for (int j = 0; j < 2; j++) v2[j] += __shfl_xor_sync(0xffffffffu, v2[j], 1);
                const float dot = (lane & 1) ? v2[1] : v2[0];

                // ---- 4) critical chain: tanh -> h_new -> publish ----
                float hn = 0.0f;
                if (lane < 16) {
                    const float v = a_t + dot;
                    const float cand = tanhf(v);
                    hn = fmaf(delta, cand, omdh);
                    __stcg(&g_hf[nxt][ep_b * DIM + ep_d], hn);
                    __threadfence();
                }
                BAR_REC();
                if (tid == 0) st_release_gpu(&g_flags[cta * 8], (unsigned)(t + 1));

                // ---- 5) off-chain work inside the barrier-wait window ----
                if (lane < 16) {
                    const size_t idx = ((size_t)t * BATCH + ep_b) * DIM + ep_d;
                    const float lg = logf(fabsf(hn) + 1e-12f);
                    const float sg = (hn >= 0.0f) ? 1.0f : -1.0f;
                    const float z  = hn + zbase;
                    const float sig = 1.0f / (1.0f + expf(-z));
                    d_out[OUT_OFF + idx]                         = hn * (z * sig);
                    d_out[LOGH_OFF + idx + (size_t)BATCH * DIM]  = lg;
                    d_out[SIGNH_OFF + idx + (size_t)BATCH * DIM] = sg;
                    d_out[HLIN_OFF + idx]                        = hn;
                    hprev = hn;

                    const int tn2 = (t + 1 < T_STEPS) ? t + 1 : t;
                    pf_x = __ldg(&x[((size_t)tn2 * BATCH + ep_b) * DIM + ep_d]);
                }

                // ---- 6) one-hop barrier: poll all 128 producer flags ----
                if (tid < RCTAS) {
                    while (ld_acquire_gpu(&g_flags[tid * 8]) < (unsigned)(t + 1)) { }
                }
            }
        } else {
            // ===== GEMM producer: A[t2][row][gc], G[t2][row][gc] ==========
            // Two independent strict ascending-k serial fp32 chains (ILP=2),
            // bit-identical to R4's gemm_nt_kernel per-output arithmetic.
            if (t2 < T_STEPS) {
                const float* xbase = x + ((size_t)t2 * BATCH) * DIM;

                // stage chunk u -> slot (u&1): 1024 float4, 8 per thread
#define STAGE_X(u)                                                             \
                {                                                              \
                    _Pragma("unroll")                                          \
                    for (int j = 0; j < 8; j++) {                              \
                        const int i  = j * 128 + tg;                           \
                        const int r  = i >> 6;                                 \
                        const int k4 = i & 63;                                 \
                        cp_async16(xs_u32 + (uint32_t)(((u & 1) * XSLOTF +     \
                                       r * XPITCH + k4 * 4) * 4),              \
                                   xbase + (size_t)r * DIM + (u) * 256 + k4 * 4);\
                    }                                                          \
                    cp_async_commit();                                         \
                }

                STAGE_X(0);
                STAGE_X(1);

                const float* wa_row = Ws + gc * WPITCH;
                const float* wd_row = Ws + (8 + gc) * WPITCH;
                float sA = 0.0f, sG = 0.0f;

#pragma unroll
                for (int u = 0; u < 4; u++) {
                    if (u < 3) cp_async_wait<1>(); else cp_async_wait<0>();
                    BAR_GEMM();
                    const float* xrow = xs + (u & 1) * XSLOTF + grow * XPITCH;
#pragma unroll 8
                    for (int k4 = 0; k4 < 64; k4++) {
                        const float4 xv = *(const float4*)&xrow[k4 * 4];
                        const float4 wa = *(const float4*)&wa_row[u * 256 + k4 * 4];
                        const float4 wd = *(const float4*)&wd_row[u * 256 + k4 * 4];
                        sA = fmaf(xv.x, wa.x, sA);  sG = fmaf(xv.x, wd.x, sG);
                        sA = fmaf(xv.y, wa.y, sA);  sG = fmaf(xv.y, wd.y, sG);
                        sA = fmaf(xv.z, wa.z, sA);  sG = fmaf(xv.z, wd.z, sG);
                        sA = fmaf(xv.w, wa.w, sA);  sG = fmaf(xv.w, wd.w, sG);
                    }
                    BAR_GEMM();          // slot fully consumed by all threads
                    if (u < 2) STAGE_X(u + 2);
                }
#undef STAGE_X

                sA += gba;
                sG += gbd;
                const int slot = (t2 % 3) * 256 + grow * 16;
                AGr[slot + gc]     = sA;
                AGr[slot + 8 + gc] = sG;
            }
        }

        __syncthreads();   // step boundary: orders AGr ring handoff + xs reuse
    }
}

// ---------------------------------------------------------------------------
extern "C" void kernel_launch(void* const* d_in, const int* in_sizes, int n_in,
                              void* d_out, int out_size)
{
    const float* x       = (const float*)d_in[0];
    const float* W_x     = (const float*)d_in[1];
    const float* R_h     = (const float*)d_in[2];
    const float* W_delta = (const float*)d_in[3];
    const float* b       = (const float*)d_in[4];
    const float* b_delta = (const float*)d_in[5];
    const float* b_gate  = (const float*)d_in[6];
    float* out = (float*)d_out;

    cudaFuncSetAttribute(fused_kernel,
                         cudaFuncAttributeMaxDynamicSharedMemorySize, SM_BYTES);

    init_kernel<<<64, 256>>>(out);
    fused_kernel<<<RCTAS, NTHR, SM_BYTES>>>(x, W_x, W_delta, R_h, b, b_delta,
                                            b_gate, out);
}

// round 15
// speedup vs baseline: 2.5124x; 1.0039x over previous
#include <cuda_runtime.h>
#include <cstdint>

// Problem constants
#define T_STEPS 2048
#define BATCH   16
#define DIM     1024

constexpr size_t SZ_TBD  = (size_t)T_STEPS * BATCH * DIM;        // 33,554,432
constexpr size_t SZ_T1BD = (size_t)(T_STEPS + 1) * BATCH * DIM;  // 33,570,816

constexpr size_t OUT_OFF   = 0;
constexpr size_t LOGH_OFF  = SZ_TBD;
constexpr size_t SIGNH_OFF = SZ_TBD + SZ_T1BD;
constexpr size_t HLIN_OFF  = SZ_TBD + 2 * SZ_T1BD;               // total 134,250,496

#define RCTAS 128
#define CPC   8    // output columns per CTA
#define NTHR  384  // 8 rec warps + 4 gemm warps

// Scratch: h broadcast ping-pong + per-CTA flags (A/G never leave SMEM)
__device__ float g_hf[2][BATCH * DIM];
__device__ unsigned g_flags[RCTAS * 8];

// ---- primitives -----------------------------------------------------------
__device__ __forceinline__ void st_release_gpu(unsigned* p, unsigned v) {
    asm volatile("st.release.gpu.global.u32 [%0], %1;" :: "l"(p), "r"(v) : "memory");
}
__device__ __forceinline__ unsigned ld_acquire_gpu(const unsigned* p) {
    unsigned v;
    asm volatile("ld.acquire.gpu.global.u32 %0, [%1];" : "=r"(v) : "l"(p) : "memory");
    return v;
}
__device__ __forceinline__ void st_release_cta_shared(uint32_t a, unsigned v) {
    asm volatile("st.release.cta.shared.u32 [%0], %1;" :: "r"(a), "r"(v) : "memory");
}
__device__ __forceinline__ unsigned ld_acquire_cta_shared(uint32_t a) {
    unsigned v;
    asm volatile("ld.acquire.cta.shared.u32 %0, [%1];" : "=r"(v) : "r"(a) : "memory");
    return v;
}
__device__ __forceinline__ void cp_async16(uint32_t dst, const void* src) {
    asm volatile("cp.async.cg.shared.global [%0], [%1], 16;" :: "r"(dst), "l"(src));
}
__device__ __forceinline__ void cp_async_commit() {
    asm volatile("cp.async.commit_group;");
}
template <int N>
__device__ __forceinline__ void cp_async_wait() {
    asm volatile("cp.async.wait_group %0;" :: "n"(N));
}
#define BAR_REC()  asm volatile("bar.sync 1, 256;" ::: "memory")
#define BAR_GEMM() asm volatile("bar.sync 2, 128;" ::: "memory")

// ---------------------------------------------------------------------------
// Init: flags, h0, log_h[0]/sign_h[0] rows
// ---------------------------------------------------------------------------
__global__ void init_kernel(float* __restrict__ d_out) {
    int tid = blockIdx.x * blockDim.x + threadIdx.x;
    if (tid < RCTAS * 8) g_flags[tid] = 0u;
    const int n = BATCH * DIM;
    for (int i = tid; i < n; i += gridDim.x * blockDim.x) {
        g_hf[0][i] = 0.0f;
        d_out[LOGH_OFF  + i] = -1e4f;   // LOG_ZERO
        d_out[SIGNH_OFF + i] = 1.0f;
    }
}

// ---------------------------------------------------------------------------
// Fused persistent kernel: 128 CTAs x 384 threads (12 warps), DECOUPLED groups.
//   warps 0-7 : recurrence — arithmetic BIT-IDENTICAL to the passing R4 kernel
//   warps 8-11: GEMM producer — runs its OWN loop up to 2 steps ahead;
//               handshake with rec via SMEM counters (release/acquire .cta).
//               Thread owns A[t2][row][c] and G[t2][row][c] as two strict
//               ascending-k serial fp32 FMA chains (bit-identical to R4 gemm).
//               Warp = 8 rows x 4 cols (x LDS broadcast-dup, conflict-free).
//
// SMEM (floats):
//   hs  [16*1024]        @ 0      (64 KB)     h broadcast
//   Rs  [ 8*1024]        @ 16384  (32 KB)     R_h slice
//   Ws  [16*1028]        @ 24576  (64.25 KB)  rows 0-7 W_x, 8-15 W_delta
//   xs  [2][16*260]      @ 41024  (32.5 KB)   x chunk ring (pitch 260)
//   AGr [3][16][16]      @ 49344  ( 3 KB)     A/G ring (slot, batch, col16)
//   cnt [2]              @ 50112  rec_done, gemm_done
// ---------------------------------------------------------------------------
#define HS_OFF   0
#define RS_OFF   16384
#define WS_OFF   24576
#define WPITCH   1028
#define XS_OFF   41024
#define XPITCH   260
#define XSLOTF   (16 * XPITCH)     // 4160 floats per slot
#define AGR_OFF  49344
#define CNT_OFF  50112
#define SM_FLOATS 50120
#define SM_BYTES  (SM_FLOATS * 4)  // 200480

__global__ __launch_bounds__(NTHR, 1)
void fused_kernel(const float* __restrict__ x,
                  const float* __restrict__ W_x, const float* __restrict__ W_d,
                  const float* __restrict__ Rh,
                  const float* __restrict__ b,   const float* __restrict__ b_d,
                  const float* __restrict__ b_gate, float* __restrict__ d_out)
{
    extern __shared__ float sm[];
    float* hs  = sm + HS_OFF;
    float* Rs  = sm + RS_OFF;
    float* Ws  = sm + WS_OFF;
    float* xs  = sm + XS_OFF;
    float* AGr = sm + AGR_OFF;
    unsigned* cnt = (unsigned*)(sm + CNT_OFF);   // [0]=rec_done, [1]=gemm_done

    const int cta  = blockIdx.x;
    const int tid  = threadIdx.x;
    const int warp = tid >> 5;
    const int lane = tid & 31;
    const bool isRec = (warp < 8);

    if (tid == 0) { cnt[0] = 0u; cnt[1] = 0u; }

    // ---- R slice into SMEM (all threads) ----
    {
        const float4* src = (const float4*)(Rh + (size_t)cta * CPC * DIM);
        float4* dst = (float4*)Rs;
        for (int i = tid; i < CPC * DIM / 4; i += NTHR) dst[i] = src[i];
    }
    // ---- W slice into SMEM: Ws[c][k], c 0-7 = W_x rows, 8-15 = W_d rows ----
    {
        for (int i = tid; i < 16 * 256; i += NTHR) {   // float4 units
            const int c  = i >> 8;          // 0..15
            const int k4 = i & 255;         // 0..255
            const float* src = (c < 8)
                ? (W_x + (size_t)(cta * CPC + c) * DIM + k4 * 4)
                : (W_d + (size_t)(cta * CPC + (c - 8)) * DIM + k4 * 4);
            *(float4*)&Ws[c * WPITCH + k4 * 4] = __ldg((const float4*)src);
        }
    }

    const uint32_t hs_u32  = (uint32_t)__cvta_generic_to_shared(hs);
    const uint32_t xs_u32  = (uint32_t)__cvta_generic_to_shared(xs);
    const uint32_t cnt_u32 = (uint32_t)__cvta_generic_to_shared(cnt);

    __syncthreads();   // setup complete; groups diverge permanently below

    if (isRec) {
        // ================= recurrence (threads 0-255) =================
        const int bb = warp & 3;
        const int dd = warp >> 2;
        const int ep_b  = bb * 4 + (lane >> 2);
        const int ep_lc = (dd & 1) * 4 + (lane & 3);
        const int ep_d  = cta * CPC + ep_lc;
        float bg = 0.f, hprev = 0.f, pf_x = 0.f;
        if (lane < 16) {
            bg   = b_gate[ep_d];
            pf_x = __ldg(&x[(size_t)ep_b * DIM + ep_d]);   // x for t=0
        }
        int cp_row[4], cp_c4[4];
#pragma unroll
        for (int j = 0; j < 4; j++) {
            int f = tid + j * 256;
            cp_row[j] = f >> 6;
            cp_c4[j]  = f & 63;
        }

        for (int t = 0; t < T_STEPS; t++) {
            const int cur = t & 1, nxt = cur ^ 1;

            // ---- 1) issue h broadcast first (fills poll window) ----
            {
                const float4* src = (const float4*)g_hf[cur];
#pragma unroll
                for (int u = 0; u < 4; u++) {
#pragma unroll
                    for (int j = 0; j < 4; j++) {
                        const int off = cp_row[j] * 256 + u * 64 + cp_c4[j];
                        cp_async16(hs_u32 + (uint32_t)off * 16, src + off);
                    }
                    cp_async_commit();
                }
            }

            // ---- 0) wait for AGr[t], read + precompute ----
            while (ld_acquire_cta_shared(cnt_u32 + 4) < (unsigned)(t + 1)) { }
            float a_t = 0.f, delta = 0.f, omdh = 0.f, zbase = 0.f;
            if (lane < 16) {
                const int slot = (t % 3) * 256 + ep_b * 16;
                a_t = AGr[slot + ep_lc];
                const float g_t = AGr[slot + 8 + ep_lc];
                delta = 1.0f / (1.0f + expf(-g_t));
                omdh  = (1.0f - delta) * hprev;
                zbase = pf_x + bg;
            }

            // ---- 2) dot (h from hs, R from Rs), chunk-overlapped ----
            float acc[4][4];
#pragma unroll
            for (int i = 0; i < 4; i++)
#pragma unroll
                for (int j = 0; j < 4; j++) acc[i][j] = 0.0f;

#pragma unroll
            for (int u = 0; u < 4; u++) {
                if      (u == 0) cp_async_wait<3>();
                else if (u == 1) cp_async_wait<2>();
                else if (u == 2) cp_async_wait<1>();
                else             cp_async_wait<0>();
                BAR_REC();
                if (u == 0 && tid == 0)   // all rec threads past AGr read
                    st_release_cta_shared(cnt_u32, (unsigned)(t + 1));
#pragma unroll
                for (int v = 0; v < 2; v++) {
                    const int ur = u * 2 + v;
                    const int k  = ur * 128 + lane * 4;
                    float4 hv[4], rv[4];
#pragma unroll
                    for (int i = 0; i < 4; i++)
                        hv[i] = *(const float4*)&hs[(bb * 4 + i) * DIM + k];
#pragma unroll
                    for (int j = 0; j < 4; j++)
                        rv[j] = *(const float4*)&Rs[(dd * 4 + j) * DIM + k];
#pragma unroll
                    for (int i = 0; i < 4; i++)
#pragma unroll
                        for (int j = 0; j < 4; j++) {
                            acc[i][j] += hv[i].x * rv[j].x;
                            acc[i][j] += hv[i].y * rv[j].y;
                            acc[i][j] += hv[i].z * rv[j].z;
                            acc[i][j] += hv[i].w * rv[j].w;
                        }
                }
            }

            // ---- 3) folded shuffle reduce: value i*4+j -> lane ----
            float* v16 = &acc[0][0];
#pragma unroll
            for (int v = 0; v < 16; v++) v16[v] += __shfl_xor_sync(0xffffffffu, v16[v], 16);
#pragma unroll
            for (int v = 0; v < 16; v++) v16[v] += __shfl_xor_sync(0xffffffffu, v16[v], 8);
            float v8[8];
#pragma unroll
            for (int j = 0; j < 8; j++) v8[j] = (lane & 8) ? v16[8 + j] : v16[j];
#pragma unroll
            for (int j = 0; j < 8; j++) v8[j] += __shfl_xor_sync(0xffffffffu, v8[j], 4);
            float v4[4];
#pragma unroll
            for (int j = 0; j < 4; j++) v4[j] = (lane & 4) ? v8[4 + j] : v8[j];
#pragma unroll
            for (int j = 0; j < 4; j++) v4[j] += __shfl_xor_sync(0xffffffffu, v4[j], 2);
            float v2[2];
#pragma unroll
            for (int j = 0; j < 2; j++) v2[j] = (lane & 2) ? v4[2 + j] : v4[j];
#pragma unroll
            for (int j = 0; j < 2; j++) v2[j] += __shfl_xor_sync(0xffffffffu, v2[j], 1);
            const float dot = (lane & 1) ? v2[1] : v2[0];

            // ---- 4) critical chain: tanh -> h_new -> publish ----
            float hn = 0.0f;
            if (lane < 16) {
                const float v = a_t + dot;
                const float cand = tanhf(v);
                hn = fmaf(delta, cand, omdh);
                __stcg(&g_hf[nxt][ep_b * DIM + ep_d], hn);
                __threadfence();
            }
            BAR_REC();
            if (tid == 0) st_release_gpu(&g_flags[cta * 8], (unsigned)(t + 1));

            // ---- 5) off-chain work inside the barrier-wait window ----
            if (lane < 16) {
                const size_t idx = ((size_t)t * BATCH + ep_b) * DIM + ep_d;
                const float lg = logf(fabsf(hn) + 1e-12f);
                const float sg = (hn >= 0.0f) ? 1.0f : -1.0f;
                const float z  = hn + zbase;
                const float sig = 1.0f / (1.0f + expf(-z));
                d_out[OUT_OFF + idx]                         = hn * (z * sig);
                d_out[LOGH_OFF + idx + (size_t)BATCH * DIM]  = lg;
                d_out[SIGNH_OFF + idx + (size_t)BATCH * DIM] = sg;
                d_out[HLIN_OFF + idx]                        = hn;
                hprev = hn;

                const int tn2 = (t + 1 < T_STEPS) ? t + 1 : t;
                pf_x = __ldg(&x[((size_t)tn2 * BATCH + ep_b) * DIM + ep_d]);
            }

            // ---- 6) one-hop barrier: poll all 128 producer flags ----
            if (tid < RCTAS) {
                while (ld_acquire_gpu(&g_flags[tid * 8]) < (unsigned)(t + 1)) { }
            }
            BAR_REC();
        }
    } else {
        // ================= GEMM producer (threads 256-383) =================
        const int tg    = tid - 256;              // 0..127
        const int gwarp = tg >> 5;                // 0..3
        const int grow  = (gwarp >> 1) * 8 + (lane & 7);   // 0..15
        const int gc    = (gwarp & 1) * 4 + (lane >> 3);   // 0..7
        const float gba = __ldg(&b[cta * CPC + gc]);
        const float gbd = __ldg(&b_d[cta * CPC + gc]);
        const float* wa_row = Ws + gc * WPITCH;
        const float* wd_row = Ws + (8 + gc) * WPITCH;

        for (int t2 = 0; t2 < T_STEPS; t2++) {
            const float* xbase = x + ((size_t)t2 * BATCH) * DIM;

#define STAGE_X(u)                                                             \
            {                                                                  \
                _Pragma("unroll")                                              \
                for (int j = 0; j < 8; j++) {                                  \
                    const int i  = j * 128 + tg;                               \
                    const int r  = i >> 6;                                     \
                    const int k4 = i & 63;                                     \
                    cp_async16(xs_u32 + (uint32_t)(((u & 1) * XSLOTF +         \
                                   r * XPITCH + k4 * 4) * 4),                  \
                               xbase + (size_t)r * DIM + (u) * 256 + k4 * 4);  \
                }                                                              \
                cp_async_commit();                                             \
            }

            STAGE_X(0);
            STAGE_X(1);

            float sA = 0.0f, sG = 0.0f;
#pragma unroll
            for (int u = 0; u < 4; u++) {
                if (u < 3) cp_async_wait<1>(); else cp_async_wait<0>();
                BAR_GEMM();
                const float* xrow = xs + (u & 1) * XSLOTF + grow * XPITCH;
#pragma unroll 8
                for (int k4 = 0; k4 < 64; k4++) {
                    const float4 xv = *(const float4*)&xrow[k4 * 4];
                    const float4 wa = *(const float4*)&wa_row[u * 256 + k4 * 4];
                    const float4 wd = *(const float4*)&wd_row[u * 256 + k4 * 4];
                    sA = fmaf(xv.x, wa.x, sA);  sG = fmaf(xv.x, wd.x, sG);
                    sA = fmaf(xv.y, wa.y, sA);  sG = fmaf(xv.y, wd.y, sG);
                    sA = fmaf(xv.z, wa.z, sA);  sG = fmaf(xv.z, wd.z, sG);
                    sA = fmaf(xv.w, wa.w, sA);  sG = fmaf(xv.w, wd.w, sG);
                }
                BAR_GEMM();          // slot fully consumed by all gemm threads
                if (u < 2) STAGE_X(u + 2);
            }
#undef STAGE_X

            sA += gba;
            sG += gbd;

            // wait until rec consumed the slot we are about to overwrite
            if (t2 >= 3) {
                while (ld_acquire_cta_shared(cnt_u32) < (unsigned)(t2 - 2)) { }
            }
            const int slot = (t2 % 3) * 256 + grow * 16;
            AGr[slot + gc]     = sA;
            AGr[slot + 8 + gc] = sG;
            BAR_GEMM();              // all AGr writes done (bar drains STS)
            if (tg == 0)
                st_release_cta_shared(cnt_u32 + 4, (unsigned)(t2 + 1));
        }
    }
}

// ---------------------------------------------------------------------------
extern "C" void kernel_launch(void* const* d_in, const int* in_sizes, int n_in,
                              void* d_out, int out_size)
{
    const float* x       = (const float*)d_in[0];
    const float* W_x     = (const float*)d_in[1];
    const float* R_h     = (const float*)d_in[2];
    const float* W_delta = (const float*)d_in[3];
    const float* b       = (const float*)d_in[4];
    const float* b_delta = (const float*)d_in[5];
    const float* b_gate  = (const float*)d_in[6];
    float* out = (float*)d_out;

    cudaFuncSetAttribute(fused_kernel,
                         cudaFuncAttributeMaxDynamicSharedMemorySize, SM_BYTES);

    init_kernel<<<64, 256>>>(out);
    fused_kernel<<<RCTAS, NTHR, SM_BYTES>>>(x, W_x, W_delta, R_h, b, b_delta,
                                            b_gate, out);
}

// round 16
// speedup vs baseline: 2.6912x; 1.0712x over previous
#include <cuda_runtime.h>
#include <cstdint>

// Problem constants
#define T_STEPS 2048
#define BATCH   16
#define DIM     1024

constexpr size_t SZ_TBD  = (size_t)T_STEPS * BATCH * DIM;        // 33,554,432
constexpr size_t SZ_T1BD = (size_t)(T_STEPS + 1) * BATCH * DIM;  // 33,570,816

constexpr size_t OUT_OFF   = 0;
constexpr size_t LOGH_OFF  = SZ_TBD;
constexpr size_t SIGNH_OFF = SZ_TBD + SZ_T1BD;
constexpr size_t HLIN_OFF  = SZ_TBD + 2 * SZ_T1BD;               // total 134,250,496

#define RCTAS 128
#define CPC   8    // output columns per CTA
#define NTHR  512  // 8 rec warps + 8 gemm warps

// Scratch: h broadcast ping-pong + per-CTA flags (A/G never leave SMEM)
__device__ float g_hf[2][BATCH * DIM];
__device__ unsigned g_flags[RCTAS * 8];

// ---- primitives -----------------------------------------------------------
__device__ __forceinline__ void st_release_gpu(unsigned* p, unsigned v) {
    asm volatile("st.release.gpu.global.u32 [%0], %1;" :: "l"(p), "r"(v) : "memory");
}
__device__ __forceinline__ unsigned ld_acquire_gpu(const unsigned* p) {
    unsigned v;
    asm volatile("ld.acquire.gpu.global.u32 %0, [%1];" : "=r"(v) : "l"(p) : "memory");
    return v;
}
__device__ __forceinline__ void st_release_cta_shared(uint32_t a, unsigned v) {
    asm volatile("st.release.cta.shared.u32 [%0], %1;" :: "r"(a), "r"(v) : "memory");
}
__device__ __forceinline__ unsigned ld_acquire_cta_shared(uint32_t a) {
    unsigned v;
    asm volatile("ld.acquire.cta.shared.u32 %0, [%1];" : "=r"(v) : "r"(a) : "memory");
    return v;
}
__device__ __forceinline__ void cp_async16(uint32_t dst, const void* src) {
    asm volatile("cp.async.cg.shared.global [%0], [%1], 16;" :: "r"(dst), "l"(src));
}
__device__ __forceinline__ void cp_async_commit() {
    asm volatile("cp.async.commit_group;");
}
template <int N>
__device__ __forceinline__ void cp_async_wait() {
    asm volatile("cp.async.wait_group %0;" :: "n"(N));
}
#define BAR_REC()  asm volatile("bar.sync 1, 256;" ::: "memory")
#define BAR_GEMM() asm volatile("bar.sync 2, 256;" ::: "memory")

// ---------------------------------------------------------------------------
// Init: flags, h0, log_h[0]/sign_h[0] rows
// ---------------------------------------------------------------------------
__global__ void init_kernel(float* __restrict__ d_out) {
    int tid = blockIdx.x * blockDim.x + threadIdx.x;
    if (tid < RCTAS * 8) g_flags[tid] = 0u;
    const int n = BATCH * DIM;
    for (int i = tid; i < n; i += gridDim.x * blockDim.x) {
        g_hf[0][i] = 0.0f;
        d_out[LOGH_OFF  + i] = -1e4f;   // LOG_ZERO
        d_out[SIGNH_OFF + i] = 1.0f;
    }
}

// ---------------------------------------------------------------------------
// Fused persistent kernel: 128 CTAs x 512 threads (16 warps), decoupled groups.
//   warps 0-7 : recurrence — arithmetic BIT-IDENTICAL to the passing R4 kernel
//   warps 8-15: GEMM producer — 256 threads, ONE output each (A or G column).
//               Processes a PAIR of steps (t2, t2+1) per pass: two independent
//               strict ascending-k serial fp32 FMA chains (ILP=2, W load
//               shared by both steps).  Bit-identical to R4 gemm arithmetic.
//               Warp = 4 rows x 8 cols -> x and W LDS conflict-free+broadcast.
//
// SMEM (floats):
//   hs  [16*1024]      @ 0      (64 KB)     h broadcast
//   Rs  [ 8*1024]      @ 16384  (32 KB)     R_h slice
//   Ws  [16*1028]      @ 24576  (64.25 KB)  rows 0-7 W_x, 8-15 W_delta
//   xs  [4][16*132]    @ 41024  (33 KB)     x 128-k chunk slots:
//                                           slot (u&1) = step t2, 2+(u&1) = t2+1
//   AGr [4][16][16]    @ 49472  ( 4 KB)     A/G ring (slot=t%4, batch, col16)
//   cnt [2]            @ 50496  rec_done, gemm_done
// ---------------------------------------------------------------------------
#define HS_OFF   0
#define RS_OFF   16384
#define WS_OFF   24576
#define WPITCH   1028
#define XS_OFF   41024
#define XPITCH   132
#define XSLOTF   (16 * XPITCH)     // 2112 floats per slot
#define AGR_OFF  49472
#define CNT_OFF  50496
#define SM_FLOATS 50504
#define SM_BYTES  (SM_FLOATS * 4)  // 202016

__global__ __launch_bounds__(NTHR, 1)
void fused_kernel(const float* __restrict__ x,
                  const float* __restrict__ W_x, const float* __restrict__ W_d,
                  const float* __restrict__ Rh,
                  const float* __restrict__ b,   const float* __restrict__ b_d,
                  const float* __restrict__ b_gate, float* __restrict__ d_out)
{
    extern __shared__ float sm[];
    float* hs  = sm + HS_OFF;
    float* Rs  = sm + RS_OFF;
    float* Ws  = sm + WS_OFF;
    float* xs  = sm + XS_OFF;
    float* AGr = sm + AGR_OFF;
    unsigned* cnt = (unsigned*)(sm + CNT_OFF);   // [0]=rec_done, [1]=gemm_done

    const int cta  = blockIdx.x;
    const int tid  = threadIdx.x;
    const int warp = tid >> 5;
    const int lane = tid & 31;
    const bool isRec = (warp < 8);

    if (tid == 0) { cnt[0] = 0u; cnt[1] = 0u; }

    // ---- R slice into SMEM (all threads) ----
    {
        const float4* src = (const float4*)(Rh + (size_t)cta * CPC * DIM);
        float4* dst = (float4*)Rs;
        for (int i = tid; i < CPC * DIM / 4; i += NTHR) dst[i] = src[i];
    }
    // ---- W slice into SMEM: Ws[c][k], c 0-7 = W_x rows, 8-15 = W_d rows ----
    {
        for (int i = tid; i < 16 * 256; i += NTHR) {   // float4 units
            const int c  = i >> 8;          // 0..15
            const int k4 = i & 255;         // 0..255
            const float* src = (c < 8)
                ? (W_x + (size_t)(cta * CPC + c) * DIM + k4 * 4)
                : (W_d + (size_t)(cta * CPC + (c - 8)) * DIM + k4 * 4);
            *(float4*)&Ws[c * WPITCH + k4 * 4] = __ldg((const float4*)src);
        }
    }

    const uint32_t hs_u32  = (uint32_t)__cvta_generic_to_shared(hs);
    const uint32_t xs_u32  = (uint32_t)__cvta_generic_to_shared(xs);
    const uint32_t cnt_u32 = (uint32_t)__cvta_generic_to_shared(cnt);

    __syncthreads();   // setup complete; groups diverge permanently below

    if (isRec) {
        // ================= recurrence (threads 0-255) =================
        const int bb = warp & 3;
        const int dd = warp >> 2;
        const int ep_b  = bb * 4 + (lane >> 2);
        const int ep_lc = (dd & 1) * 4 + (lane & 3);
        const int ep_d  = cta * CPC + ep_lc;
        float bg = 0.f, hprev = 0.f, pf_x = 0.f;
        if (lane < 16) {
            bg   = b_gate[ep_d];
            pf_x = __ldg(&x[(size_t)ep_b * DIM + ep_d]);   // x for t=0
        }
        int cp_row[4], cp_c4[4];
#pragma unroll
        for (int j = 0; j < 4; j++) {
            int f = tid + j * 256;
            cp_row[j] = f >> 6;
            cp_c4[j]  = f & 63;
        }

        for (int t = 0; t < T_STEPS; t++) {
            const int cur = t & 1, nxt = cur ^ 1;

            // ---- 1) issue h broadcast first (fills wait windows) ----
            {
                const float4* src = (const float4*)g_hf[cur];
#pragma unroll
                for (int u = 0; u < 4; u++) {
#pragma unroll
                    for (int j = 0; j < 4; j++) {
                        const int off = cp_row[j] * 256 + u * 64 + cp_c4[j];
                        cp_async16(hs_u32 + (uint32_t)off * 16, src + off);
                    }
                    cp_async_commit();
                }
            }

            // ---- 0) wait for AGr[t], read + precompute ----
            while (ld_acquire_cta_shared(cnt_u32 + 4) < (unsigned)(t + 1)) { }
            float a_t = 0.f, delta = 0.f, omdh = 0.f, zbase = 0.f;
            if (lane < 16) {
                const int slot = (t & 3) * 256 + ep_b * 16;
                a_t = AGr[slot + ep_lc];
                const float g_t = AGr[slot + 8 + ep_lc];
                delta = 1.0f / (1.0f + expf(-g_t));
                omdh  = (1.0f - delta) * hprev;
                zbase = pf_x + bg;
            }

            // ---- 2) dot (h from hs, R from Rs), chunk-overlapped ----
            float acc[4][4];
#pragma unroll
            for (int i = 0; i < 4; i++)
#pragma unroll
                for (int j = 0; j < 4; j++) acc[i][j] = 0.0f;

#pragma unroll
            for (int u = 0; u < 4; u++) {
                if      (u == 0) cp_async_wait<3>();
                else if (u == 1) cp_async_wait<2>();
                else if (u == 2) cp_async_wait<1>();
                else             cp_async_wait<0>();
                BAR_REC();
                if (u == 0 && tid == 0)   // all rec threads past AGr read
                    st_release_cta_shared(cnt_u32, (unsigned)(t + 1));
#pragma unroll
                for (int v = 0; v < 2; v++) {
                    const int ur = u * 2 + v;
                    const int k  = ur * 128 + lane * 4;
                    float4 hv[4], rv[4];
#pragma unroll
                    for (int i = 0; i < 4; i++)
                        hv[i] = *(const float4*)&hs[(bb * 4 + i) * DIM + k];
#pragma unroll
                    for (int j = 0; j < 4; j++)
                        rv[j] = *(const float4*)&Rs[(dd * 4 + j) * DIM + k];
#pragma unroll
                    for (int i = 0; i < 4; i++)
#pragma unroll
                        for (int j = 0; j < 4; j++) {
                            acc[i][j] += hv[i].x * rv[j].x;
                            acc[i][j] += hv[i].y * rv[j].y;
                            acc[i][j] += hv[i].z * rv[j].z;
                            acc[i][j] += hv[i].w * rv[j].w;
                        }
                }
            }

            // ---- 3) folded shuffle reduce: value i*4+j -> lane ----
            float* v16 = &acc[0][0];
#pragma unroll
            for (int v = 0; v < 16; v++) v16[v] += __shfl_xor_sync(0xffffffffu, v16[v], 16);
#pragma unroll
            for (int v = 0; v < 16; v++) v16[v] += __shfl_xor_sync(0xffffffffu, v16[v], 8);
            float v8[8];
#pragma unroll
            for (int j = 0; j < 8; j++) v8[j] = (lane & 8) ? v16[8 + j] : v16[j];
#pragma unroll
            for (int j = 0; j < 8; j++) v8[j] += __shfl_xor_sync(0xffffffffu, v8[j], 4);
            float v4[4];
#pragma unroll
            for (int j = 0; j < 4; j++) v4[j] = (lane & 4) ? v8[4 + j] : v8[j];
#pragma unroll
            for (int j = 0; j < 4; j++) v4[j] += __shfl_xor_sync(0xffffffffu, v4[j], 2);
            float v2[2];
#pragma unroll
            for (int j = 0; j < 2; j++) v2[j] = (lane & 2) ? v4[2 + j] : v4[j];
#pragma unroll
            for (int j = 0; j < 2; j++) v2[j] += __shfl_xor_sync(0xffffffffu, v2[j], 1);
            const float dot = (lane & 1) ? v2[1] : v2[0];

            // ---- 4) critical chain: tanh -> h_new -> publish ----
            float hn = 0.0f;
            if (lane < 16) {
                const float v = a_t + dot;
                const float cand = tanhf(v);
                hn = fmaf(delta, cand, omdh);
                __stcg(&g_hf[nxt][ep_b * DIM + ep_d], hn);
                __threadfence();
            }
            BAR_REC();
            if (tid == 0) st_release_gpu(&g_flags[cta * 8], (unsigned)(t + 1));

            // ---- 5) off-chain work inside the barrier-wait window ----
            if (lane < 16) {
                const size_t idx = ((size_t)t * BATCH + ep_b) * DIM + ep_d;
                const float lg = logf(fabsf(hn) + 1e-12f);
                const float sg = (hn >= 0.0f) ? 1.0f : -1.0f;
                const float z  = hn + zbase;
                const float sig = 1.0f / (1.0f + expf(-z));
                d_out[OUT_OFF + idx]                         = hn * (z * sig);
                d_out[LOGH_OFF + idx + (size_t)BATCH * DIM]  = lg;
                d_out[SIGNH_OFF + idx + (size_t)BATCH * DIM] = sg;
                d_out[HLIN_OFF + idx]                        = hn;
                hprev = hn;

                const int tn2 = (t + 1 < T_STEPS) ? t + 1 : t;
                pf_x = __ldg(&x[((size_t)tn2 * BATCH + ep_b) * DIM + ep_d]);
            }

            // ---- 6) one-hop barrier: poll all 128 producer flags ----
            if (tid < RCTAS) {
                while (ld_acquire_gpu(&g_flags[tid * 8]) < (unsigned)(t + 1)) { }
            }
            BAR_REC();
        }
    } else {
        // ================= GEMM producer (threads 256-511) =================
        const int tg    = tid - 256;              // 0..255
        const int gwarp = tg >> 5;                // 0..7
        const int grow  = (gwarp >> 1) * 4 + (lane >> 3);      // 0..15
        const int gcol  = (gwarp & 1) * 8 + (lane & 7);        // 0..15 (A/G)
        const float gbias = (gcol < 8) ? __ldg(&b[cta * CPC + gcol])
                                       : __ldg(&b_d[cta * CPC + (gcol - 8)]);
        const float* wrow = Ws + gcol * WPITCH;

        for (int t2 = 0; t2 < T_STEPS; t2 += 2) {
            const float* xbA = x + ((size_t)t2 * BATCH) * DIM;
            const float* xbB = x + ((size_t)(t2 + 1) * BATCH) * DIM;

            // stage 128-k chunk u for BOTH steps into slots (u&1), 2+(u&1)
#define STAGE_X2(u)                                                            \
            {                                                                  \
                _Pragma("unroll")                                              \
                for (int j = 0; j < 2; j++) {                                  \
                    const int i  = j * 256 + tg;                               \
                    const int r  = i >> 5;                                     \
                    const int k4 = i & 31;                                     \
                    const size_t so = (size_t)r * DIM + (u) * 128 + k4 * 4;    \
                    const uint32_t dof = (uint32_t)(r * XPITCH + k4 * 4) * 4;  \
                    cp_async16(xs_u32 + (uint32_t)(((u) & 1) * XSLOTF * 4) + dof, \
                               xbA + so);                                      \
                    cp_async16(xs_u32 + (uint32_t)((2 + ((u) & 1)) * XSLOTF * 4) + dof, \
                               xbB + so);                                      \
                }                                                              \
                cp_async_commit();                                             \
            }

            STAGE_X2(0);
            STAGE_X2(1);

            float sA = 0.0f, sB = 0.0f;   // chains for t2 and t2+1
#pragma unroll 2
            for (int u = 0; u < 8; u++) {
                if (u < 7) cp_async_wait<1>(); else cp_async_wait<0>();
                BAR_GEMM();
                const float* xrA = xs + (u & 1) * XSLOTF + grow * XPITCH;
                const float* xrB = xs + (2 + (u & 1)) * XSLOTF + grow * XPITCH;
                const float* wr  = wrow + u * 128;
#pragma unroll 8
                for (int k4 = 0; k4 < 32; k4++) {
                    const float4 wv = *(const float4*)&wr[k4 * 4];
                    const float4 xa = *(const float4*)&xrA[k4 * 4];
                    const float4 xb = *(const float4*)&xrB[k4 * 4];
                    sA = fmaf(xa.x, wv.x, sA);  sB = fmaf(xb.x, wv.x, sB);
                    sA = fmaf(xa.y, wv.y, sA);  sB = fmaf(xb.y, wv.y, sB);
                    sA = fmaf(xa.z, wv.z, sA);  sB = fmaf(xb.z, wv.z, sB);
                    sA = fmaf(xa.w, wv.w, sA);  sB = fmaf(xb.w, wv.w, sB);
                }
                BAR_GEMM();          // slot fully consumed by all gemm threads
                if (u < 6) STAGE_X2(u + 2);
            }
#undef STAGE_X2

            sA += gbias;
            sB += gbias;

            // wait until rec consumed the slots we are about to overwrite
            if (t2 >= 4) {
                while (ld_acquire_cta_shared(cnt_u32) < (unsigned)(t2 - 2)) { }
            }
            AGr[(t2 & 3) * 256 + grow * 16 + gcol]       = sA;
            AGr[((t2 + 1) & 3) * 256 + grow * 16 + gcol] = sB;
            BAR_GEMM();              // all AGr writes done (bar drains STS)
            if (tg == 0)
                st_release_cta_shared(cnt_u32 + 4, (unsigned)(t2 + 2));
        }
    }
}

// ---------------------------------------------------------------------------
extern "C" void kernel_launch(void* const* d_in, const int* in_sizes, int n_in,
                              void* d_out, int out_size)
{
    const float* x       = (const float*)d_in[0];
    const float* W_x     = (const float*)d_in[1];
    const float* R_h     = (const float*)d_in[2];
    const float* W_delta = (const float*)d_in[3];
    const float* b       = (const float*)d_in[4];
    const float* b_delta = (const float*)d_in[5];
    const float* b_gate  = (const float*)d_in[6];
    float* out = (float*)d_out;

    cudaFuncSetAttribute(fused_kernel,
                         cudaFuncAttributeMaxDynamicSharedMemorySize, SM_BYTES);

    init_kernel<<<64, 256>>>(out);
    fused_kernel<<<RCTAS, NTHR, SM_BYTES>>>(x, W_x, W_delta, R_h, b, b_delta,
                                            b_gate, out);
}